// round 1
// baseline (speedup 1.0000x reference)
#include <cuda_runtime.h>
#include <stdint.h>

// Problem constants (fixed by the dataset)
#define BATCH   4
#define NPTS    16384
#define NCTR    4096
#define NSAMP   32
#define NCH     64
#define NOUTCH  67          // 3 xyz-offset channels + 64 feature channels
#define RADIUS2 0.04f       // 0.2^2

// Scratch: idx (2 MB) and transposed features (B,N,C) (16 MB)
__device__ int   g_idx[BATCH * NCTR * NSAMP];
__device__ float g_ft [BATCH * (size_t)NPTS * NCH];

// ---------------------------------------------------------------------------
// Kernel 1: ball query, one warp per center.
// Warp scans points 32-at-a-time in index order; ballot gives hit mask;
// ordered slot positions via prefix popc; early exit once 32 hits collected.
// Matches reference semantics: first NSAMP hits in index order, remaining
// slots filled with first hit index, all-zero if no hits.
// Distance uses the reference's expanded form: cn2 + xn2 - 2*cross.
// ---------------------------------------------------------------------------
__global__ void ball_query_kernel(const float* __restrict__ xyz,
                                  const float* __restrict__ new_xyz)
{
    const int warp_global = (blockIdx.x * blockDim.x + threadIdx.x) >> 5;
    const int lane = threadIdx.x & 31;
    if (warp_global >= BATCH * NCTR) return;

    const int b = warp_global / NCTR;
    const int p = warp_global % NCTR;

    const float* ctr = new_xyz + (size_t)(b * NCTR + p) * 3;
    const float cx = ctr[0], cy = ctr[1], cz = ctr[2];
    const float cn2 = cx * cx + cy * cy + cz * cz;

    const float* pts = xyz + (size_t)b * NPTS * 3;
    int* out = g_idx + (size_t)warp_global * NSAMP;

    int  cnt   = 0;
    int  first = 0;
    bool found = false;

    for (int k0 = 0; k0 < NPTS; k0 += 32) {
        const int k = k0 + lane;             // NPTS % 32 == 0, no bounds check
        const float xx = pts[k * 3 + 0];
        const float xy = pts[k * 3 + 1];
        const float xz = pts[k * 3 + 2];
        const float xn2   = xx * xx + xy * xy + xz * xz;
        const float cross = cx * xx + cy * xy + cz * xz;
        const float d2    = cn2 + xn2 - 2.0f * cross;   // reference's form

        const bool hit = d2 < RADIUS2;
        const unsigned mask = __ballot_sync(0xFFFFFFFFu, hit);

        if (!found && mask) {
            first = k0 + __ffs(mask) - 1;
            found = true;
        }
        const int pos = cnt + __popc(mask & ((1u << lane) - 1u));
        if (hit && pos < NSAMP) out[pos] = k;
        cnt += __popc(mask);
        if (cnt >= NSAMP) break;
    }

    const int fill = found ? first : 0;
    const int have = cnt < NSAMP ? cnt : NSAMP;
    if (lane >= have) out[lane] = fill;
}

// ---------------------------------------------------------------------------
// Kernel 2: transpose features (B,C,N) -> (B,N,C) so the gather reads each
// point's 64-channel row contiguously (256 B), killing the 8x sector
// amplification a (B,C,N) gather would incur.
// ---------------------------------------------------------------------------
__global__ void transpose_kernel(const float* __restrict__ f)
{
    __shared__ float tile[32][33];
    const int b  = blockIdx.z;
    const int c0 = blockIdx.y * 32;
    const int n0 = blockIdx.x * 32;
    const int tx = threadIdx.x;
    const int ty = threadIdx.y;      // block (32, 8)

#pragma unroll
    for (int i = 0; i < 32; i += 8)
        tile[ty + i][tx] = f[((size_t)b * NCH + (c0 + ty + i)) * NPTS + n0 + tx];

    __syncthreads();

#pragma unroll
    for (int i = 0; i < 32; i += 8)
        g_ft[((size_t)b * NPTS + (n0 + ty + i)) * NCH + c0 + tx] = tile[tx][ty + i];
}

// ---------------------------------------------------------------------------
// Kernel 3: gather + concat. One warp per center; lane = sample slot.
// xyz channels: out[c] = xyz[idx][c] - center[c]            (c = 0..2)
// feature channels: out[3+c] = ft[idx][c]                   (c = 0..63)
// Feature reads are two float4s (32 B) per lane per step -> full-sector
// utilization. Writes are warp-coalesced 128 B rows in the S dimension.
// ---------------------------------------------------------------------------
__global__ void gather_kernel(const float* __restrict__ xyz,
                              const float* __restrict__ new_xyz,
                              float* __restrict__ out)
{
    const int warp_global = (blockIdx.x * blockDim.x + threadIdx.x) >> 5;
    const int lane = threadIdx.x & 31;
    if (warp_global >= BATCH * NCTR) return;

    const int b = warp_global / NCTR;
    const int p = warp_global % NCTR;

    const int j = g_idx[(size_t)warp_global * NSAMP + lane];

    // xyz-offset channels
    const float* pt  = xyz     + ((size_t)b * NPTS + j) * 3;
    const float* ctr = new_xyz + ((size_t)b * NCTR + p) * 3;
    const float px = pt[0] - ctr[0];
    const float py = pt[1] - ctr[1];
    const float pz = pt[2] - ctr[2];

    const size_t PS = (size_t)NCTR * NSAMP;                  // channel stride
    const size_t ob = (size_t)b * NOUTCH * PS + (size_t)p * NSAMP + lane;
    out[ob + 0 * PS] = px;
    out[ob + 1 * PS] = py;
    out[ob + 2 * PS] = pz;

    // feature channels from transposed layout (contiguous 256 B per point)
    const float4* fr = reinterpret_cast<const float4*>(
        g_ft + ((size_t)b * NPTS + j) * NCH);
    const size_t of = ob + 3 * PS;

#pragma unroll
    for (int c4 = 0; c4 < 16; c4 += 2) {
        const float4 a  = fr[c4];
        const float4 bb = fr[c4 + 1];
        const int c = c4 * 4;
        out[of + (size_t)(c + 0) * PS] = a.x;
        out[of + (size_t)(c + 1) * PS] = a.y;
        out[of + (size_t)(c + 2) * PS] = a.z;
        out[of + (size_t)(c + 3) * PS] = a.w;
        out[of + (size_t)(c + 4) * PS] = bb.x;
        out[of + (size_t)(c + 5) * PS] = bb.y;
        out[of + (size_t)(c + 6) * PS] = bb.z;
        out[of + (size_t)(c + 7) * PS] = bb.w;
    }
}

// ---------------------------------------------------------------------------
extern "C" void kernel_launch(void* const* d_in, const int* in_sizes, int n_in,
                              void* d_out, int out_size)
{
    const float* xyz      = (const float*)d_in[0];   // (4,16384,3)
    const float* new_xyz  = (const float*)d_in[1];   // (4,4096,3)
    const float* features = (const float*)d_in[2];   // (4,64,16384)
    float* out = (float*)d_out;                      // (4,67,4096,32)

    // 1 warp per center, 8 warps per block
    const int nwarps = BATCH * NCTR;                 // 16384
    const int blocks = nwarps / 8;                   // 2048

    ball_query_kernel<<<blocks, 256>>>(xyz, new_xyz);

    dim3 tgrid(NPTS / 32, NCH / 32, BATCH);          // (512, 2, 4)
    transpose_kernel<<<tgrid, dim3(32, 8)>>>(features);

    gather_kernel<<<blocks, 256>>>(xyz, new_xyz, out);
}